// round 13
// baseline (speedup 1.0000x reference)
#include <cuda_runtime.h>
#include <cuda_fp16.h>
#include <cstdint>

#define NB    8
#define DIM   512
#define LSEQ  2304
#define FD    512
#define MTOT  (NB * LSEQ)         // 18432
#define MF    ((size_t)MTOT * FD) // 9437184
#define EPSN  1e-5f
#define SCORE_SCALE 0.044194173824159216f   // 1/sqrt(512)

typedef __half fp16;

// ---------------- scratch (device globals) ----------------
__device__ fp16  g_flat_h[MF];                       // x^T rounded once
__device__ fp16  g_Wh[3][FD * DIM];                  // W rounded once
__device__ fp16  g_Qh[MF];
__device__ fp16  g_Kh[MF];
__device__ fp16  g_Vh[MF];
__device__ fp16  g_Ph[(size_t)NB * LSEQ * LSEQ];     // probs fp16
__device__ float g_S[(size_t)NB * LSEQ * LSEQ];      // scores fp32; front doubles as fp16 raw QKV

// ---------------- PTX helpers ----------------
__device__ __forceinline__ uint32_t smem_u32(const void* p) {
    uint32_t a;
    asm("{ .reg .u64 t; cvta.to.shared.u64 t, %1; cvt.u32.u64 %0, t; }" : "=r"(a) : "l"(p));
    return a;
}
__device__ __forceinline__ void cp16(uint32_t dst, const void* src) {
    asm volatile("cp.async.cg.shared.global [%0], [%1], 16;" :: "r"(dst), "l"(src));
}
#define CP_COMMIT() asm volatile("cp.async.commit_group;" ::: "memory")
#define CP_WAIT(N)  asm volatile("cp.async.wait_group %0;" :: "n"(N) : "memory")

__device__ __forceinline__ void ldsm4(uint32_t* r, uint32_t addr) {
    asm volatile("ldmatrix.sync.aligned.m8n8.x4.shared.b16 {%0,%1,%2,%3}, [%4];"
                 : "=r"(r[0]), "=r"(r[1]), "=r"(r[2]), "=r"(r[3]) : "r"(addr));
}
__device__ __forceinline__ void ldsm4t(uint32_t* r, uint32_t addr) {
    asm volatile("ldmatrix.sync.aligned.m8n8.x4.trans.shared.b16 {%0,%1,%2,%3}, [%4];"
                 : "=r"(r[0]), "=r"(r[1]), "=r"(r[2]), "=r"(r[3]) : "r"(addr));
}
__device__ __forceinline__ void mma16816(float* c, const uint32_t* a, const uint32_t* b) {
    asm volatile("mma.sync.aligned.m16n8k16.row.col.f32.f16.f16.f32 "
                 "{%0,%1,%2,%3}, {%4,%5,%6,%7}, {%8,%9}, {%0,%1,%2,%3};"
                 : "+f"(c[0]), "+f"(c[1]), "+f"(c[2]), "+f"(c[3])
                 : "r"(a[0]), "r"(a[1]), "r"(a[2]), "r"(a[3]), "r"(b[0]), "r"(b[1]));
}

// ---------------- SMEM geometry ----------------
// A tile: 128 rows x 64 fp16 = 128B/row, XOR-swizzled = 16384 B
// B tile (TRB=1): 64 rows x 128 fp16 = 256B/row, chunk-XOR swizzled = 16384 B
#define TB 16384
#define STAGEB (2 * TB)           // A | B
#define NSTAGE 3
#define GEMM_SMEM (NSTAGE * STAGEB)   // 96 KB -> 2 CTAs/SM

// ===========================================================================
// 1-term fp16 GEMM, fp32 accum, 512 threads, warp tile 32x32, 3-stage pipe.
// C[m,n] = sum_k A[m,k]*B'[n,k]
//   TRB=0: B stored (n,k) K-major with ld == K (same as A geometry)
//   TRB=1: B stored (k,n) row-major with row stride ldb  -> ldmatrix.trans
// EPI 0: fp16 out = tanh(acc + bias[z]); EPI 1: fp32 out = acc*scale; EPI 2: fp32 out
// ===========================================================================
template <int EPI, int TRB>
__global__ void __launch_bounds__(512, 2) gemmN(
    const fp16* __restrict__ A, const fp16* __restrict__ B,
    float* __restrict__ C, fp16* __restrict__ Ch,
    const float* __restrict__ b0, const float* __restrict__ b1,
    const float* __restrict__ b2,
    int K, int ldb, int ldc,
    long long sA, long long sB, long long sC, float scale)
{
    extern __shared__ char smem[];
    const uint32_t sbase = smem_u32(smem);
    const int tid  = threadIdx.x;
    const int lane = tid & 31, wid = tid >> 5;       // 16 warps
    const int wm = wid >> 2, wn = wid & 3;           // 4m x 4n, warp tile 32x32

    const int m0 = blockIdx.y * 128;
    const int f0 = blockIdx.x * 128;
    A += (long long)blockIdx.z * sA + (size_t)m0 * K;
    if (TRB == 0) B += (long long)blockIdx.z * sB + (size_t)f0 * K;
    else          B += (long long)blockIdx.z * sB + f0;
    if (EPI == 0) Ch += (long long)blockIdx.z * sC;
    else          C  += (long long)blockIdx.z * sC;
    const float* bias = (EPI == 0)
        ? ((blockIdx.z == 0) ? b0 : (blockIdx.z == 1) ? b1 : b2) : nullptr;

    // A cp.async mapping: thread t -> row = t>>2, chunk pair = (t&3)*2 + q
    const int arow  = tid >> 2;
    const int acp   = (tid & 3) * 2;
    const int axor  = arow & 7;
    const size_t gA0 = (size_t)arow * K + acp * 8;
    const uint32_t aRow128 = (uint32_t)(arow * 128);

    // B cp.async mapping (TRB=1): thread t -> row = t>>3 (64 rows x 256B)
    const int brow  = tid >> 3;
    const int bcp   = (tid & 7) * 2;
    const int bxor  = brow & 7;
    const uint32_t bRow256 = (uint32_t)(brow * 256);

    // ldmatrix lane mapping
    const int j = lane & 7, g = lane >> 3;
    const int aSel = g >> 1, bSel = g & 1;
    const uint32_t aRowB = (uint32_t)((wm * 32 + (g & 1) * 8 + j) * 128);
    const uint32_t bRowB = (uint32_t)((wn * 32 + (g >> 1) * 8 + j) * 128);  // TRB=0
    const uint32_t tRowB = (uint32_t)((((g & 1) * 8) + j) * 256);           // TRB=1
    const int tChunk0 = wn * 4 + (g >> 1);

    float acc[2][4][4];
#pragma unroll
    for (int a = 0; a < 2; a++)
#pragma unroll
        for (int b = 0; b < 4; b++)
#pragma unroll
            for (int r = 0; r < 4; r++) acc[a][b][r] = 0.0f;

    const int NIT = K >> 6;   // K / 64

    auto load_stage = [&](int st, int k0) {
        const uint32_t abase = sbase + st * STAGEB + aRow128;
#pragma unroll
        for (int q = 0; q < 2; ++q) {
            const uint32_t d = abase + (uint32_t)(((acp + q) ^ axor) * 16);
            cp16(d, A + gA0 + k0 + q * 8);
            if (TRB == 0)
                cp16(d + TB, B + gA0 + k0 + q * 8);   // same geometry, ld == K
        }
        if (TRB == 1) {
            const uint32_t bbase = sbase + st * STAGEB + TB + bRow256;
            const fp16* src = B + (size_t)(k0 + brow) * ldb + bcp * 8;
#pragma unroll
            for (int q = 0; q < 2; ++q)
                cp16(bbase + (uint32_t)(((bcp + q) ^ bxor) * 16), src + q * 8);
        }
    };

    // prologue: stages 0 and 1
    load_stage(0, 0);
    CP_COMMIT();
    if (NIT > 1) load_stage(1, 64);
    CP_COMMIT();

    int stC = 0;              // compute stage
    int stL = 2;              // next load target stage
    for (int it = 0; it < NIT; ++it) {
        CP_WAIT(1);
        __syncthreads();
        const uint32_t sb = sbase + stC * STAGEB;
#pragma unroll
        for (int c = 0; c < 4; ++c) {          // four k16 blocks per stage
            uint32_t bh[8];
            if (TRB == 0) {
                const uint32_t bPhys = (uint32_t)((((2 * c) + bSel) ^ j) * 16);
                ldsm4(bh,     sb + TB + bRowB + bPhys);
                ldsm4(bh + 4, sb + TB + bRowB + 16 * 128 + bPhys);
            } else {
                const uint32_t bb = sb + TB + c * 4096 + tRowB;
                ldsm4t(bh,     bb + (uint32_t)(((tChunk0)     ^ j) * 16));
                ldsm4t(bh + 4, bb + (uint32_t)(((tChunk0 + 2) ^ j) * 16));
            }
            const uint32_t aPhys = (uint32_t)((((2 * c) + aSel) ^ j) * 16);
#pragma unroll
            for (int mi = 0; mi < 2; ++mi) {
                uint32_t ah[4];
                ldsm4(ah, sb + aRowB + mi * (16 * 128) + aPhys);
#pragma unroll
                for (int ni = 0; ni < 4; ++ni) mma16816(acc[mi][ni], ah, &bh[ni * 2]);
            }
        }
        __syncthreads();
        if (it + 2 < NIT) load_stage(stL, (it + 2) * 64);
        CP_COMMIT();                            // unconditional: keeps wait ladder aligned
        stC = (stC == NSTAGE - 1) ? 0 : stC + 1;
        stL = (stL == NSTAGE - 1) ? 0 : stL + 1;
    }

    // epilogue
    const int qp = lane & 3, rr = lane >> 2;
#pragma unroll
    for (int mi = 0; mi < 2; ++mi) {
#pragma unroll
        for (int ni = 0; ni < 4; ++ni) {
            const int row = m0 + wm * 32 + mi * 16 + rr;
            const int col = f0 + wn * 32 + ni * 8 + qp * 2;
            float2 v0 = make_float2(acc[mi][ni][0], acc[mi][ni][1]);
            float2 v1 = make_float2(acc[mi][ni][2], acc[mi][ni][3]);
            if (EPI == 0) {
                float2 b = *(const float2*)(bias + col);
                __half2 h0 = __floats2half2_rn(tanhf(v0.x + b.x), tanhf(v0.y + b.y));
                __half2 h1 = __floats2half2_rn(tanhf(v1.x + b.x), tanhf(v1.y + b.y));
                *(__half2*)(Ch + (size_t)row * ldc + col)       = h0;
                *(__half2*)(Ch + (size_t)(row + 8) * ldc + col) = h1;
            } else {
                if (EPI == 1) {
                    v0.x *= scale; v0.y *= scale; v1.x *= scale; v1.y *= scale;
                }
                *(float2*)(C + (size_t)row * ldc + col)       = v0;
                *(float2*)(C + (size_t)(row + 8) * ldc + col) = v1;
            }
        }
    }
}

// ===========================================================================
// x (N,D,L) -> flat (M,D) fp16 rounded once. 64d x 32l tiles:
// reads 128B/row and writes 128B/row, both fully coalesced.
// ===========================================================================
__global__ __launch_bounds__(256) void xhalf(const float* __restrict__ x,
                                             fp16* __restrict__ oh)
{
    __shared__ float t[64][33];
    const int z = blockIdx.z;
    const float* in = x + (size_t)z * DIM * LSEQ;
    const int l0 = blockIdx.x * 32, d0 = blockIdx.y * 64;
    const int xx = threadIdx.x & 31, yy = threadIdx.x >> 5;   // 32 x 8

    // load 64 d-rows x 32 l-cols
#pragma unroll
    for (int i = 0; i < 64; i += 8)
        t[yy + i][xx] = in[(size_t)(d0 + yy + i) * LSEQ + l0 + xx];
    __syncthreads();

    // write: warp yy handles l-rows yy, yy+8, yy+16, yy+24; lane writes half2 at d = xx*2
#pragma unroll
    for (int i = 0; i < 32; i += 8) {
        const int l = yy + i;
        __half2 h = __floats2half2_rn(t[xx * 2][l], t[xx * 2 + 1][l]);
        *(__half2*)(oh + (size_t)(z * LSEQ + l0 + l) * DIM + d0 + xx * 2) = h;
    }
}

// weights: round once to fp16, vectorized; grid.y selects q/k/v
__global__ __launch_bounds__(256) void wsplit(const float* __restrict__ wq,
                                              const float* __restrict__ wk,
                                              const float* __restrict__ wv,
                                              fp16* __restrict__ h)
{
    const int n4 = (FD * DIM) / 4;
    const float* w = (blockIdx.y == 0) ? wq : (blockIdx.y == 1) ? wk : wv;
    int i = blockIdx.x * 256 + threadIdx.x;
    if (i < n4) {
        float4 v = ((const float4*)w)[i];
        __half2 h0 = __floats2half2_rn(v.x, v.y);
        __half2 h1 = __floats2half2_rn(v.z, v.w);
        uint2 u = make_uint2(*(uint32_t*)&h0, *(uint32_t*)&h1);
        ((uint2*)(h + (size_t)blockIdx.y * FD * DIM))[i] = u;
    }
}

// ===========================================================================
// Analytic double instance norm, warp-per-row (no block sync):
//   z = (x-mu) * r1 * r2,  r1=rsqrt(var+eps), r2=rsqrt(var*r1*r1+eps)
// ===========================================================================
__global__ __launch_bounds__(128) void inorm_half(const fp16* __restrict__ raw,
                                                  fp16* __restrict__ qh,
                                                  fp16* __restrict__ kh,
                                                  fp16* __restrict__ vh)
{
    const int which = blockIdx.y;
    const int row   = blockIdx.x * 4 + (threadIdx.x >> 5);
    const int lane  = threadIdx.x & 31;
    raw += (size_t)which * MF;
    fp16* oh = (which == 0) ? qh : (which == 1) ? kh : vh;

    const uint4* src = (const uint4*)(raw + (size_t)row * FD);
    uint4 u0 = src[lane * 2];
    uint4 u1 = src[lane * 2 + 1];

    float2 f[8];
    f[0] = __half22float2(*(__half2*)&u0.x); f[1] = __half22float2(*(__half2*)&u0.y);
    f[2] = __half22float2(*(__half2*)&u0.z); f[3] = __half22float2(*(__half2*)&u0.w);
    f[4] = __half22float2(*(__half2*)&u1.x); f[5] = __half22float2(*(__half2*)&u1.y);
    f[6] = __half22float2(*(__half2*)&u1.z); f[7] = __half22float2(*(__half2*)&u1.w);

    float s = 0.0f, sq = 0.0f;
#pragma unroll
    for (int i = 0; i < 8; i++) {
        s  += f[i].x + f[i].y;
        sq += f[i].x * f[i].x + f[i].y * f[i].y;
    }
#pragma unroll
    for (int o = 16; o > 0; o >>= 1) {
        s  += __shfl_xor_sync(0xffffffffu, s,  o);
        sq += __shfl_xor_sync(0xffffffffu, sq, o);
    }

    const float mu  = s * (1.0f / FD);
    float var = fmaxf(sq * (1.0f / FD) - mu * mu, 0.0f);
    const float r1  = rsqrtf(var + EPSN);
    const float v2  = var * r1 * r1;
    const float r2  = rsqrtf(v2 + EPSN);
    const float sc  = r1 * r2;

    uint4 o0, o1;
    __half2* po = (__half2*)&o0;
#pragma unroll
    for (int i = 0; i < 4; i++)
        po[i] = __floats2half2_rn((f[i].x - mu) * sc, (f[i].y - mu) * sc);
    __half2* p1 = (__half2*)&o1;
#pragma unroll
    for (int i = 0; i < 4; i++)
        p1[i] = __floats2half2_rn((f[4 + i].x - mu) * sc, (f[4 + i].y - mu) * sc);

    uint4* dst = (uint4*)(oh + (size_t)row * FD);
    dst[lane * 2]     = o0;
    dst[lane * 2 + 1] = o1;
}

// ===========================================================================
// softmax: fp32 scores row -> fp16 prob row
// ===========================================================================
__global__ __launch_bounds__(256) void softmax_half(const float* __restrict__ S,
                                                    fp16* __restrict__ ph)
{
    const float* row = S + (size_t)blockIdx.x * LSEQ;
    __shared__ float red[8];
    const int tid = threadIdx.x;

    float v[9];
    float mx = -1e30f;
#pragma unroll
    for (int i = 0; i < 9; i++) { v[i] = row[tid + i * 256]; mx = fmaxf(mx, v[i]); }
#pragma unroll
    for (int o = 16; o > 0; o >>= 1) mx = fmaxf(mx, __shfl_xor_sync(0xffffffffu, mx, o));
    if ((tid & 31) == 0) red[tid >> 5] = mx;
    __syncthreads();
    mx = red[0];
#pragma unroll
    for (int w = 1; w < 8; w++) mx = fmaxf(mx, red[w]);
    __syncthreads();

    float s = 0.0f;
#pragma unroll
    for (int i = 0; i < 9; i++) { v[i] = expf(v[i] - mx); s += v[i]; }
#pragma unroll
    for (int o = 16; o > 0; o >>= 1) s += __shfl_xor_sync(0xffffffffu, s, o);
    if ((tid & 31) == 0) red[tid >> 5] = s;
    __syncthreads();
    s = ((red[0] + red[1]) + (red[2] + red[3])) + ((red[4] + red[5]) + (red[6] + red[7]));
    float inv = 1.0f / s;

    size_t o0 = (size_t)blockIdx.x * LSEQ + tid;
#pragma unroll
    for (int i = 0; i < 9; i++)
        ph[o0 + i * 256] = __float2half_rn(v[i] * inv);
}

// ===========================================================================
extern "C" void kernel_launch(void* const* d_in, const int* in_sizes, int n_in,
                              void* d_out, int out_size)
{
    const float* x  = (const float*)d_in[0];
    const float* Wq = (const float*)d_in[1];
    const float* bq = (const float*)d_in[2];
    const float* Wk = (const float*)d_in[3];
    const float* bk = (const float*)d_in[4];
    const float* Wv = (const float*)d_in[5];
    const float* bv = (const float*)d_in[6];
    float* out = (float*)d_out;

    fp16 *pFh, *pWh, *pQh, *pKh, *pVh, *pPh;
    float* pS;
    cudaGetSymbolAddress((void**)&pFh, g_flat_h);
    cudaGetSymbolAddress((void**)&pWh, g_Wh);
    cudaGetSymbolAddress((void**)&pQh, g_Qh);
    cudaGetSymbolAddress((void**)&pKh, g_Kh);
    cudaGetSymbolAddress((void**)&pVh, g_Vh);
    cudaGetSymbolAddress((void**)&pPh, g_Ph);
    cudaGetSymbolAddress((void**)&pS,  g_S);

    cudaFuncSetAttribute((const void*)gemmN<0, 0>, cudaFuncAttributeMaxDynamicSharedMemorySize, GEMM_SMEM);
    cudaFuncSetAttribute((const void*)gemmN<1, 0>, cudaFuncAttributeMaxDynamicSharedMemorySize, GEMM_SMEM);
    cudaFuncSetAttribute((const void*)gemmN<2, 1>, cudaFuncAttributeMaxDynamicSharedMemorySize, GEMM_SMEM);

    const int WN = FD * DIM;
    fp16* qraw = (fp16*)pS;      // fp16 raw QKV staged in front of g_S (56MB < 170MB)

    // 1) transpose+round x, round weights
    xhalf<<<dim3(LSEQ / 32, DIM / 64, NB), 256>>>(x, pFh);
    wsplit<<<dim3((WN / 4 + 255) / 256, 3), 256>>>(Wq, Wk, Wv, pWh);

    // 2) all three projections in one launch -> fp16 raw (tanh applied)
    gemmN<0, 0><<<dim3(FD / 128, MTOT / 128, 3), 512, GEMM_SMEM>>>(
        pFh, pWh, nullptr, qraw, bq, bk, bv, DIM, DIM, FD,
        0, (long long)WN, (long long)MF, 0.f);

    // 3) analytic double inorm (warp per row) -> fp16 Q/K/V
    inorm_half<<<dim3(MTOT / 4, 3), 128>>>(qraw, pQh, pKh, pVh);

    // 4) scores = (Q K^T) * scale  (fp32, overwrites raw staging)
    gemmN<1, 0><<<dim3(LSEQ / 128, LSEQ / 128, NB), 512, GEMM_SMEM>>>(
        pQh, pKh, pS, nullptr, nullptr, nullptr, nullptr, FD, FD, LSEQ,
        (long long)LSEQ * FD, (long long)LSEQ * FD, (long long)LSEQ * LSEQ, SCORE_SCALE);

    // 5) softmax -> fp16 P
    softmax_half<<<NB * LSEQ, 256>>>(pS, pPh);

    // 6) out = P @ V, B read directly from V (k,n) via ldmatrix.trans
    gemmN<2, 1><<<dim3(FD / 128, LSEQ / 128, NB), 512, GEMM_SMEM>>>(
        pPh, pVh, out, nullptr, nullptr, nullptr, nullptr, LSEQ, FD, FD,
        (long long)LSEQ * LSEQ, (long long)LSEQ * FD, (long long)LSEQ * FD, 1.f);
}

// round 14
// speedup vs baseline: 1.0548x; 1.0548x over previous
#include <cuda_runtime.h>
#include <cuda_fp16.h>
#include <cstdint>

#define NB    8
#define DIM   512
#define LSEQ  2304
#define FD    512
#define MTOT  (NB * LSEQ)         // 18432
#define MF    ((size_t)MTOT * FD) // 9437184
#define EPSN  1e-5f
#define SCORE_SCALE 0.044194173824159216f   // 1/sqrt(512)

typedef __half fp16;

// ---------------- scratch (device globals) ----------------
__device__ fp16  g_flat_h[MF];                       // x^T rounded once
__device__ fp16  g_Wh[3][FD * DIM];                  // W rounded once
__device__ fp16  g_Qh[MF];
__device__ fp16  g_Kh[MF];
__device__ fp16  g_Vh[MF];
__device__ fp16  g_Ph[(size_t)NB * LSEQ * LSEQ];     // probs fp16
__device__ float g_S[(size_t)NB * LSEQ * LSEQ];      // scores fp32; front doubles as fp16 raw QKV

// ---------------- PTX helpers ----------------
__device__ __forceinline__ uint32_t smem_u32(const void* p) {
    uint32_t a;
    asm("{ .reg .u64 t; cvta.to.shared.u64 t, %1; cvt.u32.u64 %0, t; }" : "=r"(a) : "l"(p));
    return a;
}
__device__ __forceinline__ void cp16(uint32_t dst, const void* src) {
    asm volatile("cp.async.cg.shared.global [%0], [%1], 16;" :: "r"(dst), "l"(src));
}
#define CP_COMMIT() asm volatile("cp.async.commit_group;" ::: "memory")
#define CP_WAIT(N)  asm volatile("cp.async.wait_group %0;" :: "n"(N) : "memory")

__device__ __forceinline__ void ldsm4(uint32_t* r, uint32_t addr) {
    asm volatile("ldmatrix.sync.aligned.m8n8.x4.shared.b16 {%0,%1,%2,%3}, [%4];"
                 : "=r"(r[0]), "=r"(r[1]), "=r"(r[2]), "=r"(r[3]) : "r"(addr));
}
__device__ __forceinline__ void ldsm4t(uint32_t* r, uint32_t addr) {
    asm volatile("ldmatrix.sync.aligned.m8n8.x4.trans.shared.b16 {%0,%1,%2,%3}, [%4];"
                 : "=r"(r[0]), "=r"(r[1]), "=r"(r[2]), "=r"(r[3]) : "r"(addr));
}
__device__ __forceinline__ void mma16816(float* c, const uint32_t* a, const uint32_t* b) {
    asm volatile("mma.sync.aligned.m16n8k16.row.col.f32.f16.f16.f32 "
                 "{%0,%1,%2,%3}, {%4,%5,%6,%7}, {%8,%9}, {%0,%1,%2,%3};"
                 : "+f"(c[0]), "+f"(c[1]), "+f"(c[2]), "+f"(c[3])
                 : "r"(a[0]), "r"(a[1]), "r"(a[2]), "r"(a[3]), "r"(b[0]), "r"(b[1]));
}

// ---------------- SMEM geometry ----------------
// A tile: 128 rows x 64 fp16 = 128B/row, XOR-swizzled = 16384 B
// B tile (TRB=1): 64 rows x 128 fp16 = 256B/row, chunk-XOR swizzled = 16384 B
#define TB 16384
#define STAGEB (2 * TB)           // A | B
#define GEMM_SMEM (2 * STAGEB)    // 64 KB, 2-stage double buffer

// ===========================================================================
// 1-term fp16 GEMM, fp32 accum, 512 threads, warp tile 32x32, 2-stage pipe.
// C[m,n] = sum_k A[m,k]*B'[n,k]
//   TRB=0: B stored (n,k) K-major with ld == K (same as A geometry)
//   TRB=1: B stored (k,n) row-major with row stride ldb  -> ldmatrix.trans
// EPI 0: fp16 out = tanh(acc + bias[z]); EPI 1: fp32 out = acc*scale; EPI 2: fp32 out
// ===========================================================================
template <int EPI, int TRB>
__global__ void __launch_bounds__(512, 2) gemmN(
    const fp16* __restrict__ A, const fp16* __restrict__ B,
    float* __restrict__ C, fp16* __restrict__ Ch,
    const float* __restrict__ b0, const float* __restrict__ b1,
    const float* __restrict__ b2,
    int K, int ldb, int ldc,
    long long sA, long long sB, long long sC, float scale)
{
    extern __shared__ char smem[];
    const uint32_t sbase = smem_u32(smem);
    const int tid  = threadIdx.x;
    const int lane = tid & 31, wid = tid >> 5;       // 16 warps
    const int wm = wid >> 2, wn = wid & 3;           // 4m x 4n, warp tile 32x32

    const int m0 = blockIdx.y * 128;
    const int f0 = blockIdx.x * 128;
    A += (long long)blockIdx.z * sA + (size_t)m0 * K;
    if (TRB == 0) B += (long long)blockIdx.z * sB + (size_t)f0 * K;
    else          B += (long long)blockIdx.z * sB + f0;
    if (EPI == 0) Ch += (long long)blockIdx.z * sC;
    else          C  += (long long)blockIdx.z * sC;
    const float* bias = (EPI == 0)
        ? ((blockIdx.z == 0) ? b0 : (blockIdx.z == 1) ? b1 : b2) : nullptr;

    // A cp.async mapping: thread t -> row = t>>2, chunk pair = (t&3)*2 + q
    const int arow  = tid >> 2;
    const int acp   = (tid & 3) * 2;
    const int axor  = arow & 7;
    const size_t gA0 = (size_t)arow * K + acp * 8;
    const uint32_t aRow128 = (uint32_t)(arow * 128);

    // B cp.async mapping (TRB=1): thread t -> row = t>>3 (64 rows x 256B)
    const int brow  = tid >> 3;
    const int bcp   = (tid & 7) * 2;
    const int bxor  = brow & 7;
    const uint32_t bRow256 = (uint32_t)(brow * 256);

    // ldmatrix lane mapping
    const int j = lane & 7, g = lane >> 3;
    const int aSel = g >> 1, bSel = g & 1;
    const uint32_t aRowB = (uint32_t)((wm * 32 + (g & 1) * 8 + j) * 128);
    const uint32_t bRowB = (uint32_t)((wn * 32 + (g >> 1) * 8 + j) * 128);  // TRB=0
    const uint32_t tRowB = (uint32_t)((((g & 1) * 8) + j) * 256);           // TRB=1
    const int tChunk0 = wn * 4 + (g >> 1);

    float acc[2][4][4];
#pragma unroll
    for (int a = 0; a < 2; a++)
#pragma unroll
        for (int b = 0; b < 4; b++)
#pragma unroll
            for (int r = 0; r < 4; r++) acc[a][b][r] = 0.0f;

    const int NIT = K >> 6;   // K / 64

    auto load_stage = [&](int st, int k0) {
        const uint32_t abase = sbase + st * STAGEB + aRow128;
#pragma unroll
        for (int q = 0; q < 2; ++q) {
            const uint32_t d = abase + (uint32_t)(((acp + q) ^ axor) * 16);
            cp16(d, A + gA0 + k0 + q * 8);
            if (TRB == 0)
                cp16(d + TB, B + gA0 + k0 + q * 8);   // same geometry, ld == K
        }
        if (TRB == 1) {
            const uint32_t bbase = sbase + st * STAGEB + TB + bRow256;
            const fp16* src = B + (size_t)(k0 + brow) * ldb + bcp * 8;
#pragma unroll
            for (int q = 0; q < 2; ++q)
                cp16(bbase + (uint32_t)(((bcp + q) ^ bxor) * 16), src + q * 8);
        }
    };

    load_stage(0, 0);
    CP_COMMIT();
    if (NIT > 1) load_stage(1, 64);
    CP_COMMIT();

    for (int it = 0; it < NIT; ++it) {
        CP_WAIT(1);
        __syncthreads();
        const uint32_t sb = sbase + (it & 1) * STAGEB;
#pragma unroll
        for (int c = 0; c < 4; ++c) {          // four k16 blocks per stage
            uint32_t bh[8];
            if (TRB == 0) {
                const uint32_t bPhys = (uint32_t)((((2 * c) + bSel) ^ j) * 16);
                ldsm4(bh,     sb + TB + bRowB + bPhys);
                ldsm4(bh + 4, sb + TB + bRowB + 16 * 128 + bPhys);
            } else {
                const uint32_t bb = sb + TB + c * 4096 + tRowB;
                ldsm4t(bh,     bb + (uint32_t)(((tChunk0)     ^ j) * 16));
                ldsm4t(bh + 4, bb + (uint32_t)(((tChunk0 + 2) ^ j) * 16));
            }
            const uint32_t aPhys = (uint32_t)((((2 * c) + aSel) ^ j) * 16);
#pragma unroll
            for (int mi = 0; mi < 2; ++mi) {
                uint32_t ah[4];
                ldsm4(ah, sb + aRowB + mi * (16 * 128) + aPhys);
#pragma unroll
                for (int ni = 0; ni < 4; ++ni) mma16816(acc[mi][ni], ah, &bh[ni * 2]);
            }
        }
        __syncthreads();
        if (it + 2 < NIT) load_stage(it & 1, (it + 2) * 64);
        CP_COMMIT();
    }

    // epilogue
    const int qp = lane & 3, rr = lane >> 2;
#pragma unroll
    for (int mi = 0; mi < 2; ++mi) {
#pragma unroll
        for (int ni = 0; ni < 4; ++ni) {
            const int row = m0 + wm * 32 + mi * 16 + rr;
            const int col = f0 + wn * 32 + ni * 8 + qp * 2;
            float2 v0 = make_float2(acc[mi][ni][0], acc[mi][ni][1]);
            float2 v1 = make_float2(acc[mi][ni][2], acc[mi][ni][3]);
            if (EPI == 0) {
                float2 b = *(const float2*)(bias + col);
                __half2 h0 = __floats2half2_rn(tanhf(v0.x + b.x), tanhf(v0.y + b.y));
                __half2 h1 = __floats2half2_rn(tanhf(v1.x + b.x), tanhf(v1.y + b.y));
                *(__half2*)(Ch + (size_t)row * ldc + col)       = h0;
                *(__half2*)(Ch + (size_t)(row + 8) * ldc + col) = h1;
            } else {
                if (EPI == 1) {
                    v0.x *= scale; v0.y *= scale; v1.x *= scale; v1.y *= scale;
                }
                *(float2*)(C + (size_t)row * ldc + col)       = v0;
                *(float2*)(C + (size_t)(row + 8) * ldc + col) = v1;
            }
        }
    }
}

// ===========================================================================
// x (N,D,L) -> flat (M,D) fp16 rounded once. 64d x 32l tiles:
// reads 128B/row and writes 128B/row, both fully coalesced.
// ===========================================================================
__global__ __launch_bounds__(256) void xhalf(const float* __restrict__ x,
                                             fp16* __restrict__ oh)
{
    __shared__ float t[64][33];
    const int z = blockIdx.z;
    const float* in = x + (size_t)z * DIM * LSEQ;
    const int l0 = blockIdx.x * 32, d0 = blockIdx.y * 64;
    const int xx = threadIdx.x & 31, yy = threadIdx.x >> 5;   // 32 x 8

    // load 64 d-rows x 32 l-cols
#pragma unroll
    for (int i = 0; i < 64; i += 8)
        t[yy + i][xx] = in[(size_t)(d0 + yy + i) * LSEQ + l0 + xx];
    __syncthreads();

    // write: warp yy handles l-rows yy, yy+8, yy+16, yy+24; lane writes half2 at d = xx*2
#pragma unroll
    for (int i = 0; i < 32; i += 8) {
        const int l = yy + i;
        __half2 h = __floats2half2_rn(t[xx * 2][l], t[xx * 2 + 1][l]);
        *(__half2*)(oh + (size_t)(z * LSEQ + l0 + l) * DIM + d0 + xx * 2) = h;
    }
}

// weights: round once to fp16, vectorized; grid.y selects q/k/v
__global__ __launch_bounds__(256) void wsplit(const float* __restrict__ wq,
                                              const float* __restrict__ wk,
                                              const float* __restrict__ wv,
                                              fp16* __restrict__ h)
{
    const int n4 = (FD * DIM) / 4;
    const float* w = (blockIdx.y == 0) ? wq : (blockIdx.y == 1) ? wk : wv;
    int i = blockIdx.x * 256 + threadIdx.x;
    if (i < n4) {
        float4 v = ((const float4*)w)[i];
        __half2 h0 = __floats2half2_rn(v.x, v.y);
        __half2 h1 = __floats2half2_rn(v.z, v.w);
        uint2 u = make_uint2(*(uint32_t*)&h0, *(uint32_t*)&h1);
        ((uint2*)(h + (size_t)blockIdx.y * FD * DIM))[i] = u;
    }
}

// ===========================================================================
// Analytic double instance norm, warp-per-row (no block sync):
//   z = (x-mu) * r1 * r2,  r1=rsqrt(var+eps), r2=rsqrt(var*r1*r1+eps)
// ===========================================================================
__global__ __launch_bounds__(128) void inorm_half(const fp16* __restrict__ raw,
                                                  fp16* __restrict__ qh,
                                                  fp16* __restrict__ kh,
                                                  fp16* __restrict__ vh)
{
    const int which = blockIdx.y;
    const int row   = blockIdx.x * 4 + (threadIdx.x >> 5);
    const int lane  = threadIdx.x & 31;
    raw += (size_t)which * MF;
    fp16* oh = (which == 0) ? qh : (which == 1) ? kh : vh;

    const uint4* src = (const uint4*)(raw + (size_t)row * FD);
    uint4 u0 = src[lane * 2];
    uint4 u1 = src[lane * 2 + 1];

    float2 f[8];
    f[0] = __half22float2(*(__half2*)&u0.x); f[1] = __half22float2(*(__half2*)&u0.y);
    f[2] = __half22float2(*(__half2*)&u0.z); f[3] = __half22float2(*(__half2*)&u0.w);
    f[4] = __half22float2(*(__half2*)&u1.x); f[5] = __half22float2(*(__half2*)&u1.y);
    f[6] = __half22float2(*(__half2*)&u1.z); f[7] = __half22float2(*(__half2*)&u1.w);

    float s = 0.0f, sq = 0.0f;
#pragma unroll
    for (int i = 0; i < 8; i++) {
        s  += f[i].x + f[i].y;
        sq += f[i].x * f[i].x + f[i].y * f[i].y;
    }
#pragma unroll
    for (int o = 16; o > 0; o >>= 1) {
        s  += __shfl_xor_sync(0xffffffffu, s,  o);
        sq += __shfl_xor_sync(0xffffffffu, sq, o);
    }

    const float mu  = s * (1.0f / FD);
    float var = fmaxf(sq * (1.0f / FD) - mu * mu, 0.0f);
    const float r1  = rsqrtf(var + EPSN);
    const float v2  = var * r1 * r1;
    const float r2  = rsqrtf(v2 + EPSN);
    const float sc  = r1 * r2;

    uint4 o0, o1;
    __half2* po = (__half2*)&o0;
#pragma unroll
    for (int i = 0; i < 4; i++)
        po[i] = __floats2half2_rn((f[i].x - mu) * sc, (f[i].y - mu) * sc);
    __half2* p1 = (__half2*)&o1;
#pragma unroll
    for (int i = 0; i < 4; i++)
        p1[i] = __floats2half2_rn((f[4 + i].x - mu) * sc, (f[4 + i].y - mu) * sc);

    uint4* dst = (uint4*)(oh + (size_t)row * FD);
    dst[lane * 2]     = o0;
    dst[lane * 2 + 1] = o1;
}

// ===========================================================================
// softmax: fp32 scores row -> fp16 prob row
// ===========================================================================
__global__ __launch_bounds__(256) void softmax_half(const float* __restrict__ S,
                                                    fp16* __restrict__ ph)
{
    const float* row = S + (size_t)blockIdx.x * LSEQ;
    __shared__ float red[8];
    const int tid = threadIdx.x;

    float v[9];
    float mx = -1e30f;
#pragma unroll
    for (int i = 0; i < 9; i++) { v[i] = row[tid + i * 256]; mx = fmaxf(mx, v[i]); }
#pragma unroll
    for (int o = 16; o > 0; o >>= 1) mx = fmaxf(mx, __shfl_xor_sync(0xffffffffu, mx, o));
    if ((tid & 31) == 0) red[tid >> 5] = mx;
    __syncthreads();
    mx = red[0];
#pragma unroll
    for (int w = 1; w < 8; w++) mx = fmaxf(mx, red[w]);
    __syncthreads();

    float s = 0.0f;
#pragma unroll
    for (int i = 0; i < 9; i++) { v[i] = expf(v[i] - mx); s += v[i]; }
#pragma unroll
    for (int o = 16; o > 0; o >>= 1) s += __shfl_xor_sync(0xffffffffu, s, o);
    if ((tid & 31) == 0) red[tid >> 5] = s;
    __syncthreads();
    s = ((red[0] + red[1]) + (red[2] + red[3])) + ((red[4] + red[5]) + (red[6] + red[7]));
    float inv = 1.0f / s;

    size_t o0 = (size_t)blockIdx.x * LSEQ + tid;
#pragma unroll
    for (int i = 0; i < 9; i++)
        ph[o0 + i * 256] = __float2half_rn(v[i] * inv);
}

// ===========================================================================
extern "C" void kernel_launch(void* const* d_in, const int* in_sizes, int n_in,
                              void* d_out, int out_size)
{
    const float* x  = (const float*)d_in[0];
    const float* Wq = (const float*)d_in[1];
    const float* bq = (const float*)d_in[2];
    const float* Wk = (const float*)d_in[3];
    const float* bk = (const float*)d_in[4];
    const float* Wv = (const float*)d_in[5];
    const float* bv = (const float*)d_in[6];
    float* out = (float*)d_out;

    fp16 *pFh, *pWh, *pQh, *pKh, *pVh, *pPh;
    float* pS;
    cudaGetSymbolAddress((void**)&pFh, g_flat_h);
    cudaGetSymbolAddress((void**)&pWh, g_Wh);
    cudaGetSymbolAddress((void**)&pQh, g_Qh);
    cudaGetSymbolAddress((void**)&pKh, g_Kh);
    cudaGetSymbolAddress((void**)&pVh, g_Vh);
    cudaGetSymbolAddress((void**)&pPh, g_Ph);
    cudaGetSymbolAddress((void**)&pS,  g_S);

    cudaFuncSetAttribute((const void*)gemmN<0, 0>, cudaFuncAttributeMaxDynamicSharedMemorySize, GEMM_SMEM);
    cudaFuncSetAttribute((const void*)gemmN<1, 0>, cudaFuncAttributeMaxDynamicSharedMemorySize, GEMM_SMEM);
    cudaFuncSetAttribute((const void*)gemmN<2, 1>, cudaFuncAttributeMaxDynamicSharedMemorySize, GEMM_SMEM);

    const int WN = FD * DIM;
    fp16* qraw = (fp16*)pS;      // fp16 raw QKV staged in front of g_S (56MB < 170MB)

    // 1) transpose+round x, round weights
    xhalf<<<dim3(LSEQ / 32, DIM / 64, NB), 256>>>(x, pFh);
    wsplit<<<dim3((WN / 4 + 255) / 256, 3), 256>>>(Wq, Wk, Wv, pWh);

    // 2) all three projections in one launch -> fp16 raw (tanh applied)
    gemmN<0, 0><<<dim3(FD / 128, MTOT / 128, 3), 512, GEMM_SMEM>>>(
        pFh, pWh, nullptr, qraw, bq, bk, bv, DIM, DIM, FD,
        0, (long long)WN, (long long)MF, 0.f);

    // 3) analytic double inorm (warp per row) -> fp16 Q/K/V
    inorm_half<<<dim3(MTOT / 4, 3), 128>>>(qraw, pQh, pKh, pVh);

    // 4) scores = (Q K^T) * scale  (fp32, overwrites raw staging)
    gemmN<1, 0><<<dim3(LSEQ / 128, LSEQ / 128, NB), 512, GEMM_SMEM>>>(
        pQh, pKh, pS, nullptr, nullptr, nullptr, nullptr, FD, FD, LSEQ,
        (long long)LSEQ * FD, (long long)LSEQ * FD, (long long)LSEQ * LSEQ, SCORE_SCALE);

    // 5) softmax -> fp16 P
    softmax_half<<<NB * LSEQ, 256>>>(pS, pPh);

    // 6) out = P @ V, B read directly from V (k,n) via ldmatrix.trans
    gemmN<2, 1><<<dim3(FD / 128, LSEQ / 128, NB), 512, GEMM_SMEM>>>(
        pPh, pVh, out, nullptr, nullptr, nullptr, nullptr, LSEQ, FD, FD,
        (long long)LSEQ * LSEQ, (long long)LSEQ * FD, (long long)LSEQ * FD, 1.f);
}

// round 16
// speedup vs baseline: 1.1127x; 1.0549x over previous
#include <cuda_runtime.h>
#include <cuda_fp16.h>
#include <cstdint>

#define NB    8
#define DIM   512
#define LSEQ  2304
#define FD    512
#define MTOT  (NB * LSEQ)         // 18432
#define MF    ((size_t)MTOT * FD) // 9437184
#define LL    ((size_t)LSEQ * LSEQ)
#define EPSN  1e-5f
#define SCORE_SCALE 0.044194173824159216f   // 1/sqrt(512)
#define SMAX  4.0f                 // static exp shift (overflow only if score > 15.1)

typedef __half fp16;

// ---------------- scratch (device globals) ----------------
__device__ fp16  g_flat_h[MF];                       // x^T rounded once
__device__ fp16  g_Wh[3][FD * DIM];                  // W rounded once
__device__ fp16  g_Qh[MF];
__device__ fp16  g_Kh[MF];
__device__ fp16  g_Vh[MF];
__device__ fp16  g_E[NB * LL];                       // E' = exp(s - SMAX), fp16
__device__ float g_R[MTOT];                          // row sums of E'
__device__ fp16  g_raw[3 * MF];                      // fp16 raw QKV staging

// ---------------- PTX helpers ----------------
__device__ __forceinline__ uint32_t smem_u32(const void* p) {
    uint32_t a;
    asm("{ .reg .u64 t; cvta.to.shared.u64 t, %1; cvt.u32.u64 %0, t; }" : "=r"(a) : "l"(p));
    return a;
}
__device__ __forceinline__ void cp16(uint32_t dst, const void* src) {
    asm volatile("cp.async.cg.shared.global [%0], [%1], 16;" :: "r"(dst), "l"(src));
}
#define CP_COMMIT() asm volatile("cp.async.commit_group;" ::: "memory")
#define CP_WAIT(N)  asm volatile("cp.async.wait_group %0;" :: "n"(N) : "memory")

__device__ __forceinline__ void ldsm4(uint32_t* r, uint32_t addr) {
    asm volatile("ldmatrix.sync.aligned.m8n8.x4.shared.b16 {%0,%1,%2,%3}, [%4];"
                 : "=r"(r[0]), "=r"(r[1]), "=r"(r[2]), "=r"(r[3]) : "r"(addr));
}
__device__ __forceinline__ void ldsm4t(uint32_t* r, uint32_t addr) {
    asm volatile("ldmatrix.sync.aligned.m8n8.x4.trans.shared.b16 {%0,%1,%2,%3}, [%4];"
                 : "=r"(r[0]), "=r"(r[1]), "=r"(r[2]), "=r"(r[3]) : "r"(addr));
}
__device__ __forceinline__ void mma16816(float* c, const uint32_t* a, const uint32_t* b) {
    asm volatile("mma.sync.aligned.m16n8k16.row.col.f32.f16.f16.f32 "
                 "{%0,%1,%2,%3}, {%4,%5,%6,%7}, {%8,%9}, {%0,%1,%2,%3};"
                 : "+f"(c[0]), "+f"(c[1]), "+f"(c[2]), "+f"(c[3])
                 : "r"(a[0]), "r"(a[1]), "r"(a[2]), "r"(a[3]), "r"(b[0]), "r"(b[1]));
}

// ---------------- SMEM geometry ----------------
#define TB 16384
#define STAGEB (2 * TB)           // A | B
#define GEMM_SMEM (2 * STAGEB)    // 64 KB, 2-stage double buffer

// ===========================================================================
// 1-term fp16 GEMM, fp32 accum, 512 threads, warp tile 32x32, 2-stage pipe.
// C[m,n] = sum_k A[m,k]*B'[n,k]
//   TRB=0: B stored (n,k) K-major, ld == K.   TRB=1: B stored (k,n), trans.
// EPI 0: fp16 out = tanh(acc + bias[z])     (proj)
// EPI 1: fp16 out = exp(acc*scale - SMAX)   (scores -> E')
// EPI 2: fp32 out = acc / R[z*LSEQ + row]   (PV with softmax denominator)
// ===========================================================================
template <int EPI, int TRB>
__global__ void __launch_bounds__(512, 2) gemmN(
    const fp16* __restrict__ A, const fp16* __restrict__ B,
    float* __restrict__ C, fp16* __restrict__ Ch,
    const float* __restrict__ b0, const float* __restrict__ b1,
    const float* __restrict__ b2,
    int K, int ldb, int ldc,
    long long sA, long long sB, long long sC, float scale)
{
    extern __shared__ char smem[];
    const uint32_t sbase = smem_u32(smem);
    const int tid  = threadIdx.x;
    const int lane = tid & 31, wid = tid >> 5;
    const int wm = wid >> 2, wn = wid & 3;

    const int m0 = blockIdx.y * 128;
    const int f0 = blockIdx.x * 128;
    A += (long long)blockIdx.z * sA + (size_t)m0 * K;
    if (TRB == 0) B += (long long)blockIdx.z * sB + (size_t)f0 * K;
    else          B += (long long)blockIdx.z * sB + f0;
    if (EPI == 2) C  += (long long)blockIdx.z * sC;
    else          Ch += (long long)blockIdx.z * sC;
    const float* bias = (EPI == 0)
        ? ((blockIdx.z == 0) ? b0 : (blockIdx.z == 1) ? b1 : b2) : nullptr;
    const float* R = (EPI == 2) ? (b0 + blockIdx.z * LSEQ) : nullptr;

    const int arow  = tid >> 2;
    const int acp   = (tid & 3) * 2;
    const int axor  = arow & 7;
    const size_t gA0 = (size_t)arow * K + acp * 8;
    const uint32_t aRow128 = (uint32_t)(arow * 128);

    const int brow  = tid >> 3;
    const int bcp   = (tid & 7) * 2;
    const int bxor  = brow & 7;
    const uint32_t bRow256 = (uint32_t)(brow * 256);

    const int j = lane & 7, g = lane >> 3;
    const int aSel = g >> 1, bSel = g & 1;
    const uint32_t aRowB = (uint32_t)((wm * 32 + (g & 1) * 8 + j) * 128);
    const uint32_t bRowB = (uint32_t)((wn * 32 + (g >> 1) * 8 + j) * 128);
    const uint32_t tRowB = (uint32_t)((((g & 1) * 8) + j) * 256);
    const int tChunk0 = wn * 4 + (g >> 1);

    float acc[2][4][4];
#pragma unroll
    for (int a = 0; a < 2; a++)
#pragma unroll
        for (int b = 0; b < 4; b++)
#pragma unroll
            for (int r = 0; r < 4; r++) acc[a][b][r] = 0.0f;

    const int NIT = K >> 6;

    auto load_stage = [&](int st, int k0) {
        const uint32_t abase = sbase + st * STAGEB + aRow128;
#pragma unroll
        for (int q = 0; q < 2; ++q) {
            const uint32_t d = abase + (uint32_t)(((acp + q) ^ axor) * 16);
            cp16(d, A + gA0 + k0 + q * 8);
            if (TRB == 0)
                cp16(d + TB, B + gA0 + k0 + q * 8);
        }
        if (TRB == 1) {
            const uint32_t bbase = sbase + st * STAGEB + TB + bRow256;
            const fp16* src = B + (size_t)(k0 + brow) * ldb + bcp * 8;
#pragma unroll
            for (int q = 0; q < 2; ++q)
                cp16(bbase + (uint32_t)(((bcp + q) ^ bxor) * 16), src + q * 8);
        }
    };

    load_stage(0, 0);
    CP_COMMIT();
    if (NIT > 1) load_stage(1, 64);
    CP_COMMIT();

    for (int it = 0; it < NIT; ++it) {
        CP_WAIT(1);
        __syncthreads();
        const uint32_t sb = sbase + (it & 1) * STAGEB;
#pragma unroll
        for (int c = 0; c < 4; ++c) {
            uint32_t bh[8];
            if (TRB == 0) {
                const uint32_t bPhys = (uint32_t)((((2 * c) + bSel) ^ j) * 16);
                ldsm4(bh,     sb + TB + bRowB + bPhys);
                ldsm4(bh + 4, sb + TB + bRowB + 16 * 128 + bPhys);
            } else {
                const uint32_t bb = sb + TB + c * 4096 + tRowB;
                ldsm4t(bh,     bb + (uint32_t)(((tChunk0)     ^ j) * 16));
                ldsm4t(bh + 4, bb + (uint32_t)(((tChunk0 + 2) ^ j) * 16));
            }
            const uint32_t aPhys = (uint32_t)((((2 * c) + aSel) ^ j) * 16);
#pragma unroll
            for (int mi = 0; mi < 2; ++mi) {
                uint32_t ah[4];
                ldsm4(ah, sb + aRowB + mi * (16 * 128) + aPhys);
#pragma unroll
                for (int ni = 0; ni < 4; ++ni) mma16816(acc[mi][ni], ah, &bh[ni * 2]);
            }
        }
        __syncthreads();
        if (it + 2 < NIT) load_stage(it & 1, (it + 2) * 64);
        CP_COMMIT();
    }

    // epilogue
    const int qp = lane & 3, rr = lane >> 2;
#pragma unroll
    for (int mi = 0; mi < 2; ++mi) {
        const int row = m0 + wm * 32 + mi * 16 + rr;
        float r0inv = 1.0f, r1inv = 1.0f;
        if (EPI == 2) {
            r0inv = 1.0f / R[row];
            r1inv = 1.0f / R[row + 8];
        }
#pragma unroll
        for (int ni = 0; ni < 4; ++ni) {
            const int col = f0 + wn * 32 + ni * 8 + qp * 2;
            float2 v0 = make_float2(acc[mi][ni][0], acc[mi][ni][1]);
            float2 v1 = make_float2(acc[mi][ni][2], acc[mi][ni][3]);
            if (EPI == 0) {
                float2 b = *(const float2*)(bias + col);
                __half2 h0 = __floats2half2_rn(tanhf(v0.x + b.x), tanhf(v0.y + b.y));
                __half2 h1 = __floats2half2_rn(tanhf(v1.x + b.x), tanhf(v1.y + b.y));
                *(__half2*)(Ch + (size_t)row * ldc + col)       = h0;
                *(__half2*)(Ch + (size_t)(row + 8) * ldc + col) = h1;
            } else if (EPI == 1) {
                __half2 h0 = __floats2half2_rn(expf(v0.x * scale - SMAX),
                                               expf(v0.y * scale - SMAX));
                __half2 h1 = __floats2half2_rn(expf(v1.x * scale - SMAX),
                                               expf(v1.y * scale - SMAX));
                *(__half2*)(Ch + (size_t)row * ldc + col)       = h0;
                *(__half2*)(Ch + (size_t)(row + 8) * ldc + col) = h1;
            } else {
                v0.x *= r0inv; v0.y *= r0inv;
                v1.x *= r1inv; v1.y *= r1inv;
                *(float2*)(C + (size_t)row * ldc + col)       = v0;
                *(float2*)(C + (size_t)(row + 8) * ldc + col) = v1;
            }
        }
    }
}

// ===========================================================================
// x (N,D,L) -> flat (M,D) fp16 rounded once. 64d x 32l tiles.
// ===========================================================================
__global__ __launch_bounds__(256) void xhalf(const float* __restrict__ x,
                                             fp16* __restrict__ oh)
{
    __shared__ float t[64][33];
    const int z = blockIdx.z;
    const float* in = x + (size_t)z * DIM * LSEQ;
    const int l0 = blockIdx.x * 32, d0 = blockIdx.y * 64;
    const int xx = threadIdx.x & 31, yy = threadIdx.x >> 5;

#pragma unroll
    for (int i = 0; i < 64; i += 8)
        t[yy + i][xx] = in[(size_t)(d0 + yy + i) * LSEQ + l0 + xx];
    __syncthreads();

#pragma unroll
    for (int i = 0; i < 32; i += 8) {
        const int l = yy + i;
        __half2 h = __floats2half2_rn(t[xx * 2][l], t[xx * 2 + 1][l]);
        *(__half2*)(oh + (size_t)(z * LSEQ + l0 + l) * DIM + d0 + xx * 2) = h;
    }
}

// weights: round once to fp16, vectorized; grid.y selects q/k/v
__global__ __launch_bounds__(256) void wsplit(const float* __restrict__ wq,
                                              const float* __restrict__ wk,
                                              const float* __restrict__ wv,
                                              fp16* __restrict__ h)
{
    const int n4 = (FD * DIM) / 4;
    const float* w = (blockIdx.y == 0) ? wq : (blockIdx.y == 1) ? wk : wv;
    int i = blockIdx.x * 256 + threadIdx.x;
    if (i < n4) {
        float4 v = ((const float4*)w)[i];
        __half2 h0 = __floats2half2_rn(v.x, v.y);
        __half2 h1 = __floats2half2_rn(v.z, v.w);
        uint2 u = make_uint2(*(uint32_t*)&h0, *(uint32_t*)&h1);
        ((uint2*)(h + (size_t)blockIdx.y * FD * DIM))[i] = u;
    }
}

// ===========================================================================
// Analytic double instance norm, warp-per-row (grid.y = q/k/v)
// ===========================================================================
__global__ __launch_bounds__(128) void inorm_half(const fp16* __restrict__ raw,
                                                  fp16* __restrict__ qh,
                                                  fp16* __restrict__ kh,
                                                  fp16* __restrict__ vh)
{
    const int which = blockIdx.y;
    const int row   = blockIdx.x * 4 + (threadIdx.x >> 5);
    const int lane  = threadIdx.x & 31;
    raw += (size_t)which * MF;
    fp16* oh = (which == 0) ? qh : (which == 1) ? kh : vh;

    const uint4* src = (const uint4*)(raw + (size_t)row * FD);
    uint4 u0 = src[lane * 2];
    uint4 u1 = src[lane * 2 + 1];

    float2 f[8];
    f[0] = __half22float2(*(__half2*)&u0.x); f[1] = __half22float2(*(__half2*)&u0.y);
    f[2] = __half22float2(*(__half2*)&u0.z); f[3] = __half22float2(*(__half2*)&u0.w);
    f[4] = __half22float2(*(__half2*)&u1.x); f[5] = __half22float2(*(__half2*)&u1.y);
    f[6] = __half22float2(*(__half2*)&u1.z); f[7] = __half22float2(*(__half2*)&u1.w);

    float s = 0.0f, sq = 0.0f;
#pragma unroll
    for (int i = 0; i < 8; i++) {
        s  += f[i].x + f[i].y;
        sq += f[i].x * f[i].x + f[i].y * f[i].y;
    }
#pragma unroll
    for (int o = 16; o > 0; o >>= 1) {
        s  += __shfl_xor_sync(0xffffffffu, s,  o);
        sq += __shfl_xor_sync(0xffffffffu, sq, o);
    }

    const float mu  = s * (1.0f / FD);
    float var = fmaxf(sq * (1.0f / FD) - mu * mu, 0.0f);
    const float r1  = rsqrtf(var + EPSN);
    const float v2  = var * r1 * r1;
    const float r2  = rsqrtf(v2 + EPSN);
    const float sc  = r1 * r2;

    uint4 o0, o1;
    __half2* po = (__half2*)&o0;
#pragma unroll
    for (int i = 0; i < 4; i++)
        po[i] = __floats2half2_rn((f[i].x - mu) * sc, (f[i].y - mu) * sc);
    __half2* p1 = (__half2*)&o1;
#pragma unroll
    for (int i = 0; i < 4; i++)
        p1[i] = __floats2half2_rn((f[4 + i].x - mu) * sc, (f[4 + i].y - mu) * sc);

    uint4* dst = (uint4*)(oh + (size_t)row * FD);
    dst[lane * 2]     = o0;
    dst[lane * 2 + 1] = o1;
}

// ===========================================================================
// rowsum: R[row] = sum over LSEQ of E'[row, :]  (fp16 in, fp32 out)
// warp-per-row; lane reads 9 uint4 (72 halves), shfl-reduce.
// ===========================================================================
__global__ __launch_bounds__(128) void rowsum_half(const fp16* __restrict__ E,
                                                   float* __restrict__ R)
{
    const int row  = blockIdx.x * 4 + (threadIdx.x >> 5);
    const int lane = threadIdx.x & 31;
    const uint4* src = (const uint4*)(E + (size_t)row * LSEQ);

    float s = 0.0f;
#pragma unroll
    for (int i = 0; i < 9; i++) {
        uint4 u = src[lane + 32 * i];
        float2 a = __half22float2(*(__half2*)&u.x);
        float2 b = __half22float2(*(__half2*)&u.y);
        float2 c = __half22float2(*(__half2*)&u.z);
        float2 d = __half22float2(*(__half2*)&u.w);
        s += ((a.x + a.y) + (b.x + b.y)) + ((c.x + c.y) + (d.x + d.y));
    }
#pragma unroll
    for (int o = 16; o > 0; o >>= 1)
        s += __shfl_xor_sync(0xffffffffu, s, o);
    if (lane == 0) R[row] = s;
}

// ===========================================================================
extern "C" void kernel_launch(void* const* d_in, const int* in_sizes, int n_in,
                              void* d_out, int out_size)
{
    const float* x  = (const float*)d_in[0];
    const float* Wq = (const float*)d_in[1];
    const float* bq = (const float*)d_in[2];
    const float* Wk = (const float*)d_in[3];
    const float* bk = (const float*)d_in[4];
    const float* Wv = (const float*)d_in[5];
    const float* bv = (const float*)d_in[6];
    float* out = (float*)d_out;

    fp16 *pFh, *pWh, *pQh, *pKh, *pVh, *pE, *pRaw;
    float* pR;
    cudaGetSymbolAddress((void**)&pFh,  g_flat_h);
    cudaGetSymbolAddress((void**)&pWh,  g_Wh);
    cudaGetSymbolAddress((void**)&pQh,  g_Qh);
    cudaGetSymbolAddress((void**)&pKh,  g_Kh);
    cudaGetSymbolAddress((void**)&pVh,  g_Vh);
    cudaGetSymbolAddress((void**)&pE,   g_E);
    cudaGetSymbolAddress((void**)&pR,   g_R);
    cudaGetSymbolAddress((void**)&pRaw, g_raw);

    cudaFuncSetAttribute((const void*)gemmN<0, 0>, cudaFuncAttributeMaxDynamicSharedMemorySize, GEMM_SMEM);
    cudaFuncSetAttribute((const void*)gemmN<1, 0>, cudaFuncAttributeMaxDynamicSharedMemorySize, GEMM_SMEM);
    cudaFuncSetAttribute((const void*)gemmN<2, 1>, cudaFuncAttributeMaxDynamicSharedMemorySize, GEMM_SMEM);

    const int WN = FD * DIM;

    // 1) transpose+round x, round weights
    xhalf<<<dim3(LSEQ / 32, DIM / 64, NB), 256>>>(x, pFh);
    wsplit<<<dim3((WN / 4 + 255) / 256, 3), 256>>>(Wq, Wk, Wv, pWh);

    // 2) all three projections in one launch -> fp16 raw (tanh applied)
    gemmN<0, 0><<<dim3(FD / 128, MTOT / 128, 3), 512, GEMM_SMEM>>>(
        pFh, pWh, nullptr, pRaw, bq, bk, bv, DIM, DIM, FD,
        0, (long long)WN, (long long)MF, 0.f);

    // 3) analytic double inorm (warp per row) -> fp16 Q/K/V
    inorm_half<<<dim3(MTOT / 4, 3), 128>>>(pRaw, pQh, pKh, pVh);

    // 4) scores -> E' = exp(s*scale - SMAX), fp16
    gemmN<1, 0><<<dim3(LSEQ / 128, LSEQ / 128, NB), 512, GEMM_SMEM>>>(
        pQh, pKh, nullptr, pE, nullptr, nullptr, nullptr, FD, FD, LSEQ,
        (long long)LSEQ * FD, (long long)LSEQ * FD, (long long)LL, SCORE_SCALE);

    // 5) row sums of E'
    rowsum_half<<<MTOT / 4, 128>>>(pE, pR);

    // 6) out = (E' @ V) / R  (B read from V (k,n) via ldmatrix.trans)
    gemmN<2, 1><<<dim3(FD / 128, LSEQ / 128, NB), 512, GEMM_SMEM>>>(
        pE, pVh, out, nullptr, pR, nullptr, nullptr, LSEQ, FD, FD,
        (long long)LL, (long long)LSEQ * FD, (long long)LSEQ * FD, 1.f);
}

// round 17
// speedup vs baseline: 1.1336x; 1.0188x over previous
#include <cuda_runtime.h>
#include <cuda_fp16.h>
#include <cstdint>

#define NB    8
#define DIM   512
#define LSEQ  2304
#define FD    512
#define MTOT  (NB * LSEQ)         // 18432
#define MF    ((size_t)MTOT * FD) // 9437184
#define LL    ((size_t)LSEQ * LSEQ)
#define EPSN  1e-5f
#define SCORE_SCALE 0.044194173824159216f   // 1/sqrt(512)
#define SMAX  4.0f                 // static exp shift (overflow only if score > 15.1)

typedef __half fp16;

// ---------------- scratch (device globals) ----------------
__device__ fp16  g_flat_h[MF];                       // x^T rounded once
__device__ fp16  g_Wh[3][FD * DIM];                  // W rounded once
__device__ fp16  g_Qh[MF];
__device__ fp16  g_Kh[MF];
__device__ fp16  g_Vh[MF];
__device__ fp16  g_E[NB * LL];                       // E' = exp(s - SMAX), fp16
__device__ float g_R[MTOT];                          // row sums of E' (atomic-accumulated)
__device__ fp16  g_raw[3 * MF];                      // fp16 raw QKV staging

// ---------------- PTX helpers ----------------
__device__ __forceinline__ uint32_t smem_u32(const void* p) {
    uint32_t a;
    asm("{ .reg .u64 t; cvta.to.shared.u64 t, %1; cvt.u32.u64 %0, t; }" : "=r"(a) : "l"(p));
    return a;
}
__device__ __forceinline__ void cp16(uint32_t dst, const void* src) {
    asm volatile("cp.async.cg.shared.global [%0], [%1], 16;" :: "r"(dst), "l"(src));
}
#define CP_COMMIT() asm volatile("cp.async.commit_group;" ::: "memory")
#define CP_WAIT(N)  asm volatile("cp.async.wait_group %0;" :: "n"(N) : "memory")

__device__ __forceinline__ void ldsm4(uint32_t* r, uint32_t addr) {
    asm volatile("ldmatrix.sync.aligned.m8n8.x4.shared.b16 {%0,%1,%2,%3}, [%4];"
                 : "=r"(r[0]), "=r"(r[1]), "=r"(r[2]), "=r"(r[3]) : "r"(addr));
}
__device__ __forceinline__ void ldsm4t(uint32_t* r, uint32_t addr) {
    asm volatile("ldmatrix.sync.aligned.m8n8.x4.trans.shared.b16 {%0,%1,%2,%3}, [%4];"
                 : "=r"(r[0]), "=r"(r[1]), "=r"(r[2]), "=r"(r[3]) : "r"(addr));
}
__device__ __forceinline__ void mma16816(float* c, const uint32_t* a, const uint32_t* b) {
    asm volatile("mma.sync.aligned.m16n8k16.row.col.f32.f16.f16.f32 "
                 "{%0,%1,%2,%3}, {%4,%5,%6,%7}, {%8,%9}, {%0,%1,%2,%3};"
                 : "+f"(c[0]), "+f"(c[1]), "+f"(c[2]), "+f"(c[3])
                 : "r"(a[0]), "r"(a[1]), "r"(a[2]), "r"(a[3]), "r"(b[0]), "r"(b[1]));
}

// ---------------- SMEM geometry ----------------
#define TB 16384
#define STAGEB (2 * TB)           // A | B
#define GEMM_SMEM (2 * STAGEB)    // 64 KB, 2-stage double buffer

// ===========================================================================
// 1-term fp16 GEMM, fp32 accum, 512 threads, warp tile 32x32, 2-stage pipe.
// C[m,n] = sum_k A[m,k]*B'[n,k]
//   TRB=0: B stored (n,k) K-major, ld == K.   TRB=1: B stored (k,n), trans.
// EPI 0: fp16 out = tanh(acc + bias[z])                       (proj)
// EPI 1: fp16 out = exp(acc*scale - SMAX); atomicAdd row sums (scores -> E', R)
// EPI 2: fp32 out = acc / R[z*LSEQ + row]                     (PV)
// ===========================================================================
template <int EPI, int TRB>
__global__ void __launch_bounds__(512, 2) gemmN(
    const fp16* __restrict__ A, const fp16* __restrict__ B,
    float* __restrict__ C, fp16* __restrict__ Ch,
    const float* __restrict__ b0, const float* __restrict__ b1,
    const float* __restrict__ b2, float* __restrict__ Rsum,
    int K, int ldb, int ldc,
    long long sA, long long sB, long long sC, float scale)
{
    extern __shared__ char smem[];
    const uint32_t sbase = smem_u32(smem);
    const int tid  = threadIdx.x;
    const int lane = tid & 31, wid = tid >> 5;
    const int wm = wid >> 2, wn = wid & 3;

    const int m0 = blockIdx.y * 128;
    const int f0 = blockIdx.x * 128;
    A += (long long)blockIdx.z * sA + (size_t)m0 * K;
    if (TRB == 0) B += (long long)blockIdx.z * sB + (size_t)f0 * K;
    else          B += (long long)blockIdx.z * sB + f0;
    if (EPI == 2) C  += (long long)blockIdx.z * sC;
    else          Ch += (long long)blockIdx.z * sC;
    const float* bias = (EPI == 0)
        ? ((blockIdx.z == 0) ? b0 : (blockIdx.z == 1) ? b1 : b2) : nullptr;
    const float* R = (EPI == 2) ? (b0 + blockIdx.z * LSEQ) : nullptr;
    float* Rout = (EPI == 1) ? (Rsum + blockIdx.z * LSEQ) : nullptr;

    const int arow  = tid >> 2;
    const int acp   = (tid & 3) * 2;
    const int axor  = arow & 7;
    const size_t gA0 = (size_t)arow * K + acp * 8;
    const uint32_t aRow128 = (uint32_t)(arow * 128);

    const int brow  = tid >> 3;
    const int bcp   = (tid & 7) * 2;
    const int bxor  = brow & 7;
    const uint32_t bRow256 = (uint32_t)(brow * 256);

    const int j = lane & 7, g = lane >> 3;
    const int aSel = g >> 1, bSel = g & 1;
    const uint32_t aRowB = (uint32_t)((wm * 32 + (g & 1) * 8 + j) * 128);
    const uint32_t bRowB = (uint32_t)((wn * 32 + (g >> 1) * 8 + j) * 128);
    const uint32_t tRowB = (uint32_t)((((g & 1) * 8) + j) * 256);
    const int tChunk0 = wn * 4 + (g >> 1);

    float acc[2][4][4];
#pragma unroll
    for (int a = 0; a < 2; a++)
#pragma unroll
        for (int b = 0; b < 4; b++)
#pragma unroll
            for (int r = 0; r < 4; r++) acc[a][b][r] = 0.0f;

    const int NIT = K >> 6;

    auto load_stage = [&](int st, int k0) {
        const uint32_t abase = sbase + st * STAGEB + aRow128;
#pragma unroll
        for (int q = 0; q < 2; ++q) {
            const uint32_t d = abase + (uint32_t)(((acp + q) ^ axor) * 16);
            cp16(d, A + gA0 + k0 + q * 8);
            if (TRB == 0)
                cp16(d + TB, B + gA0 + k0 + q * 8);
        }
        if (TRB == 1) {
            const uint32_t bbase = sbase + st * STAGEB + TB + bRow256;
            const fp16* src = B + (size_t)(k0 + brow) * ldb + bcp * 8;
#pragma unroll
            for (int q = 0; q < 2; ++q)
                cp16(bbase + (uint32_t)(((bcp + q) ^ bxor) * 16), src + q * 8);
        }
    };

    load_stage(0, 0);
    CP_COMMIT();
    if (NIT > 1) load_stage(1, 64);
    CP_COMMIT();

    for (int it = 0; it < NIT; ++it) {
        CP_WAIT(1);
        __syncthreads();
        const uint32_t sb = sbase + (it & 1) * STAGEB;
#pragma unroll
        for (int c = 0; c < 4; ++c) {
            uint32_t bh[8];
            if (TRB == 0) {
                const uint32_t bPhys = (uint32_t)((((2 * c) + bSel) ^ j) * 16);
                ldsm4(bh,     sb + TB + bRowB + bPhys);
                ldsm4(bh + 4, sb + TB + bRowB + 16 * 128 + bPhys);
            } else {
                const uint32_t bb = sb + TB + c * 4096 + tRowB;
                ldsm4t(bh,     bb + (uint32_t)(((tChunk0)     ^ j) * 16));
                ldsm4t(bh + 4, bb + (uint32_t)(((tChunk0 + 2) ^ j) * 16));
            }
            const uint32_t aPhys = (uint32_t)((((2 * c) + aSel) ^ j) * 16);
#pragma unroll
            for (int mi = 0; mi < 2; ++mi) {
                uint32_t ah[4];
                ldsm4(ah, sb + aRowB + mi * (16 * 128) + aPhys);
#pragma unroll
                for (int ni = 0; ni < 4; ++ni) mma16816(acc[mi][ni], ah, &bh[ni * 2]);
            }
        }
        __syncthreads();
        if (it + 2 < NIT) load_stage(it & 1, (it + 2) * 64);
        CP_COMMIT();
    }

    // epilogue
    const int qp = lane & 3, rr = lane >> 2;
#pragma unroll
    for (int mi = 0; mi < 2; ++mi) {
        const int row = m0 + wm * 32 + mi * 16 + rr;
        float r0inv = 1.0f, r1inv = 1.0f;
        if (EPI == 2) {
            r0inv = 1.0f / R[row];
            r1inv = 1.0f / R[row + 8];
        }
        float se0 = 0.0f, se1 = 0.0f;     // EPI==1: row-sum partials
#pragma unroll
        for (int ni = 0; ni < 4; ++ni) {
            const int col = f0 + wn * 32 + ni * 8 + qp * 2;
            float2 v0 = make_float2(acc[mi][ni][0], acc[mi][ni][1]);
            float2 v1 = make_float2(acc[mi][ni][2], acc[mi][ni][3]);
            if (EPI == 0) {
                float2 b = *(const float2*)(bias + col);
                __half2 h0 = __floats2half2_rn(tanhf(v0.x + b.x), tanhf(v0.y + b.y));
                __half2 h1 = __floats2half2_rn(tanhf(v1.x + b.x), tanhf(v1.y + b.y));
                *(__half2*)(Ch + (size_t)row * ldc + col)       = h0;
                *(__half2*)(Ch + (size_t)(row + 8) * ldc + col) = h1;
            } else if (EPI == 1) {
                float e00 = expf(v0.x * scale - SMAX);
                float e01 = expf(v0.y * scale - SMAX);
                float e10 = expf(v1.x * scale - SMAX);
                float e11 = expf(v1.y * scale - SMAX);
                se0 += e00 + e01;
                se1 += e10 + e11;
                *(__half2*)(Ch + (size_t)row * ldc + col)       = __floats2half2_rn(e00, e01);
                *(__half2*)(Ch + (size_t)(row + 8) * ldc + col) = __floats2half2_rn(e10, e11);
            } else {
                v0.x *= r0inv; v0.y *= r0inv;
                v1.x *= r1inv; v1.y *= r1inv;
                *(float2*)(C + (size_t)row * ldc + col)       = v0;
                *(float2*)(C + (size_t)(row + 8) * ldc + col) = v1;
            }
        }
        if (EPI == 1) {
            // reduce over the 4 qp lanes sharing this row (lane bits 0,1)
            se0 += __shfl_xor_sync(0xffffffffu, se0, 1);
            se0 += __shfl_xor_sync(0xffffffffu, se0, 2);
            se1 += __shfl_xor_sync(0xffffffffu, se1, 1);
            se1 += __shfl_xor_sync(0xffffffffu, se1, 2);
            if (qp == 0) {
                atomicAdd(&Rout[row],     se0);
                atomicAdd(&Rout[row + 8], se1);
            }
        }
    }
}

// ===========================================================================
// x (N,D,L) -> flat (M,D) fp16 rounded once. 64d x 32l tiles.
// ===========================================================================
__global__ __launch_bounds__(256) void xhalf(const float* __restrict__ x,
                                             fp16* __restrict__ oh)
{
    __shared__ float t[64][33];
    const int z = blockIdx.z;
    const float* in = x + (size_t)z * DIM * LSEQ;
    const int l0 = blockIdx.x * 32, d0 = blockIdx.y * 64;
    const int xx = threadIdx.x & 31, yy = threadIdx.x >> 5;

#pragma unroll
    for (int i = 0; i < 64; i += 8)
        t[yy + i][xx] = in[(size_t)(d0 + yy + i) * LSEQ + l0 + xx];
    __syncthreads();

#pragma unroll
    for (int i = 0; i < 32; i += 8) {
        const int l = yy + i;
        __half2 h = __floats2half2_rn(t[xx * 2][l], t[xx * 2 + 1][l]);
        *(__half2*)(oh + (size_t)(z * LSEQ + l0 + l) * DIM + d0 + xx * 2) = h;
    }
}

// weights: round once to fp16, vectorized; grid.y selects q/k/v
__global__ __launch_bounds__(256) void wsplit(const float* __restrict__ wq,
                                              const float* __restrict__ wk,
                                              const float* __restrict__ wv,
                                              fp16* __restrict__ h)
{
    const int n4 = (FD * DIM) / 4;
    const float* w = (blockIdx.y == 0) ? wq : (blockIdx.y == 1) ? wk : wv;
    int i = blockIdx.x * 256 + threadIdx.x;
    if (i < n4) {
        float4 v = ((const float4*)w)[i];
        __half2 h0 = __floats2half2_rn(v.x, v.y);
        __half2 h1 = __floats2half2_rn(v.z, v.w);
        uint2 u = make_uint2(*(uint32_t*)&h0, *(uint32_t*)&h1);
        ((uint2*)(h + (size_t)blockIdx.y * FD * DIM))[i] = u;
    }
}

// ===========================================================================
// Analytic double instance norm, warp-per-row (grid.y = q/k/v)
// ===========================================================================
__global__ __launch_bounds__(128) void inorm_half(const fp16* __restrict__ raw,
                                                  fp16* __restrict__ qh,
                                                  fp16* __restrict__ kh,
                                                  fp16* __restrict__ vh)
{
    const int which = blockIdx.y;
    const int row   = blockIdx.x * 4 + (threadIdx.x >> 5);
    const int lane  = threadIdx.x & 31;
    raw += (size_t)which * MF;
    fp16* oh = (which == 0) ? qh : (which == 1) ? kh : vh;

    const uint4* src = (const uint4*)(raw + (size_t)row * FD);
    uint4 u0 = src[lane * 2];
    uint4 u1 = src[lane * 2 + 1];

    float2 f[8];
    f[0] = __half22float2(*(__half2*)&u0.x); f[1] = __half22float2(*(__half2*)&u0.y);
    f[2] = __half22float2(*(__half2*)&u0.z); f[3] = __half22float2(*(__half2*)&u0.w);
    f[4] = __half22float2(*(__half2*)&u1.x); f[5] = __half22float2(*(__half2*)&u1.y);
    f[6] = __half22float2(*(__half2*)&u1.z); f[7] = __half22float2(*(__half2*)&u1.w);

    float s = 0.0f, sq = 0.0f;
#pragma unroll
    for (int i = 0; i < 8; i++) {
        s  += f[i].x + f[i].y;
        sq += f[i].x * f[i].x + f[i].y * f[i].y;
    }
#pragma unroll
    for (int o = 16; o > 0; o >>= 1) {
        s  += __shfl_xor_sync(0xffffffffu, s,  o);
        sq += __shfl_xor_sync(0xffffffffu, sq, o);
    }

    const float mu  = s * (1.0f / FD);
    float var = fmaxf(sq * (1.0f / FD) - mu * mu, 0.0f);
    const float r1  = rsqrtf(var + EPSN);
    const float v2  = var * r1 * r1;
    const float r2  = rsqrtf(v2 + EPSN);
    const float sc  = r1 * r2;

    uint4 o0, o1;
    __half2* po = (__half2*)&o0;
#pragma unroll
    for (int i = 0; i < 4; i++)
        po[i] = __floats2half2_rn((f[i].x - mu) * sc, (f[i].y - mu) * sc);
    __half2* p1 = (__half2*)&o1;
#pragma unroll
    for (int i = 0; i < 4; i++)
        p1[i] = __floats2half2_rn((f[4 + i].x - mu) * sc, (f[4 + i].y - mu) * sc);

    uint4* dst = (uint4*)(oh + (size_t)row * FD);
    dst[lane * 2]     = o0;
    dst[lane * 2 + 1] = o1;
}

// ===========================================================================
extern "C" void kernel_launch(void* const* d_in, const int* in_sizes, int n_in,
                              void* d_out, int out_size)
{
    const float* x  = (const float*)d_in[0];
    const float* Wq = (const float*)d_in[1];
    const float* bq = (const float*)d_in[2];
    const float* Wk = (const float*)d_in[3];
    const float* bk = (const float*)d_in[4];
    const float* Wv = (const float*)d_in[5];
    const float* bv = (const float*)d_in[6];
    float* out = (float*)d_out;

    fp16 *pFh, *pWh, *pQh, *pKh, *pVh, *pE, *pRaw;
    float* pR;
    cudaGetSymbolAddress((void**)&pFh,  g_flat_h);
    cudaGetSymbolAddress((void**)&pWh,  g_Wh);
    cudaGetSymbolAddress((void**)&pQh,  g_Qh);
    cudaGetSymbolAddress((void**)&pKh,  g_Kh);
    cudaGetSymbolAddress((void**)&pVh,  g_Vh);
    cudaGetSymbolAddress((void**)&pE,   g_E);
    cudaGetSymbolAddress((void**)&pR,   g_R);
    cudaGetSymbolAddress((void**)&pRaw, g_raw);

    cudaFuncSetAttribute((const void*)gemmN<0, 0>, cudaFuncAttributeMaxDynamicSharedMemorySize, GEMM_SMEM);
    cudaFuncSetAttribute((const void*)gemmN<1, 0>, cudaFuncAttributeMaxDynamicSharedMemorySize, GEMM_SMEM);
    cudaFuncSetAttribute((const void*)gemmN<2, 1>, cudaFuncAttributeMaxDynamicSharedMemorySize, GEMM_SMEM);

    const int WN = FD * DIM;

    // 0) zero the row-sum accumulator (graph-capturable, no allocation)
    cudaMemsetAsync(pR, 0, MTOT * sizeof(float));

    // 1) transpose+round x, round weights
    xhalf<<<dim3(LSEQ / 32, DIM / 64, NB), 256>>>(x, pFh);
    wsplit<<<dim3((WN / 4 + 255) / 256, 3), 256>>>(Wq, Wk, Wv, pWh);

    // 2) all three projections in one launch -> fp16 raw (tanh applied)
    gemmN<0, 0><<<dim3(FD / 128, MTOT / 128, 3), 512, GEMM_SMEM>>>(
        pFh, pWh, nullptr, pRaw, bq, bk, bv, nullptr, DIM, DIM, FD,
        0, (long long)WN, (long long)MF, 0.f);

    // 3) analytic double inorm (warp per row) -> fp16 Q/K/V
    inorm_half<<<dim3(MTOT / 4, 3), 128>>>(pRaw, pQh, pKh, pVh);

    // 4) scores -> E' = exp(s*scale - SMAX) fp16, row sums accumulated into R
    gemmN<1, 0><<<dim3(LSEQ / 128, LSEQ / 128, NB), 512, GEMM_SMEM>>>(
        pQh, pKh, nullptr, pE, nullptr, nullptr, nullptr, pR, FD, FD, LSEQ,
        (long long)LSEQ * FD, (long long)LSEQ * FD, (long long)LL, SCORE_SCALE);

    // 5) out = (E' @ V) / R  (B read from V (k,n) via ldmatrix.trans)
    gemmN<2, 1><<<dim3(FD / 128, LSEQ / 128, NB), 512, GEMM_SMEM>>>(
        pE, pVh, out, nullptr, pR, nullptr, nullptr, nullptr, LSEQ, FD, FD,
        (long long)LL, (long long)LSEQ * FD, (long long)LSEQ * FD, 1.f);
}